// round 16
// baseline (speedup 1.0000x reference)
#include <cuda_runtime.h>
#include <cuda_fp16.h>
#include <cstdint>
#include <math.h>

// Problem constants
constexpr int BATCH = 2;
constexpr int SEQ   = 2048;
constexpr int DIMV  = 2048;
constexpr int NH    = 16;
constexpr int HDIM  = 128;
constexpr int MROWS = BATCH * SEQ;  // 4096
constexpr float QSCALE = 0.08838834764831845f;  // 1/sqrt(128)
constexpr float L2E    = 1.4426950408889634f;

// ---------------------------------------------------------------------------
// Device-global scratch. RULE (R3-R5 bug): device globals must NEVER be passed
// as kernel arguments from host code — GB300 ATS silently accepts the host
// shadow address. Reference them inside kernels only.
// ---------------------------------------------------------------------------
__device__ __half g_xh [MROWS * DIMV];   // fp16(x)
__device__ __half g_qh [MROWS * DIMV];   // fp16(roped,scaled q)
__device__ __half g_kh [MROWS * DIMV];   // roped k hi
__device__ __half g_km [MROWS * DIMV];   // roped k mid
__device__ __half g_vh [MROWS * DIMV];   // v hi
__device__ __half g_vm [MROWS * DIMV];   // v mid
__device__ __half g_aoh[MROWS * DIMV];   // fp16(attention out)

// Transposed split weights: [N=2048][K=2048] K-major, value = W[k][n]
__device__ __half g_wqh[DIMV * DIMV];
__device__ __half g_wqm[DIMV * DIMV];
__device__ __half g_wkh[DIMV * DIMV];
__device__ __half g_wkm[DIMV * DIMV];
__device__ __half g_wvh[DIMV * DIMV];
__device__ __half g_wvm[DIMV * DIMV];
__device__ __half g_woh[DIMV * DIMV];
__device__ __half g_wom[DIMV * DIMV];

// ---------------------------------------------------------------------------
// helpers
// ---------------------------------------------------------------------------
__device__ __forceinline__ uint32_t smem_u32(const void* p) {
    uint32_t a;
    asm("{ .reg .u64 t; cvta.to.shared.u64 t, %1; cvt.u32.u64 %0, t; }"
        : "=r"(a) : "l"(p));
    return a;
}

__device__ __forceinline__ void mma16816(float d[4], const uint32_t a[4],
                                         const uint32_t b0, const uint32_t b1) {
    asm volatile(
        "mma.sync.aligned.m16n8k16.row.col.f32.f16.f16.f32 "
        "{%0,%1,%2,%3}, {%4,%5,%6,%7}, {%8,%9}, {%0,%1,%2,%3};"
        : "+f"(d[0]), "+f"(d[1]), "+f"(d[2]), "+f"(d[3])
        : "r"(a[0]), "r"(a[1]), "r"(a[2]), "r"(a[3]), "r"(b0), "r"(b1));
}

#define LDSM_X4(r0, r1, r2, r3, addr)                                  \
    asm volatile("ldmatrix.sync.aligned.m8n8.x4.shared.b16 "           \
                 "{%0,%1,%2,%3}, [%4];"                                \
                 : "=r"(r0), "=r"(r1), "=r"(r2), "=r"(r3) : "r"(addr))

#define LDSM_X4_T(r0, r1, r2, r3, addr)                                \
    asm volatile("ldmatrix.sync.aligned.m8n8.x4.trans.shared.b16 "     \
                 "{%0,%1,%2,%3}, [%4];"                                \
                 : "=r"(r0), "=r"(r1), "=r"(r2), "=r"(r3) : "r"(addr))

#define CP16(dst, src)                                                 \
    asm volatile("cp.async.cg.shared.global [%0], [%1], 16;"           \
                 :: "r"(dst), "l"(src) : "memory")
#define CP_COMMIT()  asm volatile("cp.async.commit_group;" ::: "memory")
#define CP_WAITG(n)  asm volatile("cp.async.wait_group %0;" :: "n"(n) : "memory")

__device__ __forceinline__ float ex2f(float x) {
    float y;
    asm("ex2.approx.ftz.f32 %0, %1;" : "=f"(y) : "f"(x));
    return y;
}

__device__ __forceinline__ uint32_t pack_h2(float x, float y) {
    __half2 h = __floats2half2_rn(x, y);
    return *reinterpret_cast<uint32_t*>(&h);
}

__device__ __forceinline__ void split2h(float x, float y,
                                        uint32_t& hi, uint32_t& mid) {
    __half hx = __float2half_rn(x);
    __half hy = __float2half_rn(y);
    __half mx = __float2half_rn(x - __half2float(hx));
    __half my = __float2half_rn(y - __half2float(hy));
    hi  = (uint32_t)__half_as_ushort(hx) |
          ((uint32_t)__half_as_ushort(hy) << 16);
    mid = (uint32_t)__half_as_ushort(mx) |
          ((uint32_t)__half_as_ushort(my) << 16);
}

// ---------------------------------------------------------------------------
// Combined split kernel:
//   z in [0,3]: weight transpose + split  (w [K,N] fp32 -> [N,K] fp16 hi/mid)
//   z == 4    : x -> g_xh (fp16)
// ---------------------------------------------------------------------------
__global__ void split_all_kernel(const float* __restrict__ x,
                                 const float* __restrict__ wq,
                                 const float* __restrict__ wk,
                                 const float* __restrict__ wv,
                                 const float* __restrict__ wo)
{
    const int z = blockIdx.z;
    const int tid = threadIdx.y * 32 + threadIdx.x;

    if (z == 4) {
        const int blk = blockIdx.y * gridDim.x + blockIdx.x;
        const int base = blk * 512 + tid;
        #pragma unroll
        for (int r = 0; r < 2; r++) {
            const int i = base + r * 256;
            float4 v = ((const float4*)x)[i];
            ((uint2*)g_xh)[i] = make_uint2(pack_h2(v.x, v.y), pack_h2(v.z, v.w));
        }
        return;
    }

    const float* w = (z == 0) ? wq : (z == 1) ? wk : (z == 2) ? wv : wo;
    __half* whT = (z == 0) ? g_wqh : (z == 1) ? g_wkh : (z == 2) ? g_wvh : g_woh;
    __half* wmT = (z == 0) ? g_wqm : (z == 1) ? g_wkm : (z == 2) ? g_wvm : g_wom;

    __shared__ float t[32][33];
    const int n0 = blockIdx.x * 32;
    const int k0 = blockIdx.y * 32;
    const int tx = threadIdx.x;
    const int ty = threadIdx.y;
    #pragma unroll
    for (int i = ty; i < 32; i += 8)
        t[i][tx] = w[(size_t)(k0 + i) * DIMV + n0 + tx];
    __syncthreads();
    #pragma unroll
    for (int i = ty; i < 32; i += 8) {
        float a = t[tx][i];
        __half bh = __float2half_rn(a);
        __half bm = __float2half_rn(a - __half2float(bh));
        whT[(size_t)(n0 + i) * DIMV + k0 + tx] = bh;
        wmT[(size_t)(n0 + i) * DIMV + k0 + tx] = bm;
    }
}

// ---------------------------------------------------------------------------
// fp16 2-product GEMM core: D = Ah*(Bh+Bm). cp.async 3-stage.
// CTA 256x128, BK=32, 512 threads = 16 warps (4m x 4n), warp tile 64x32.
// Warp PHASE STAGGERING: odd warps process k-sub-steps in reverse order so
// LDSM bursts and MMA bursts from different warps overlap on the SM instead
// of phase-locking behind each __syncthreads.
// ---------------------------------------------------------------------------
constexpr int BM = 256, BN = 128, BK = 32;
constexpr int RSTRB   = 80;
constexpr int TILE_A  = 256 * RSTRB;
constexpr int TILE_Bm = 128 * RSTRB;
constexpr int OFF_BH  = TILE_A;
constexpr int OFF_BM  = TILE_A + TILE_Bm;
constexpr int STG_B   = TILE_A + 2 * TILE_Bm;
constexpr int NSTAGE  = 3;
constexpr int GSMEM   = NSTAGE * STG_B;       // 122880
constexpr int NKSTEP  = DIMV / BK;            // 64

__device__ __forceinline__ void hgemm_core(const __half* __restrict__ Ah,
                                           const __half* __restrict__ BhT,
                                           const __half* __restrict__ BmT,
                                           int brow, int bcol,
                                           float acc[4][4][4])
{
    extern __shared__ char smem[];
    constexpr int K = DIMV;
    const uint32_t sb = smem_u32(smem);

    const int tid  = threadIdx.x;
    const int wid  = tid >> 5;
    const int lane = tid & 31;
    const int wm   = wid & 3;
    const int wn   = wid >> 2;

    const int la = lane & 7;
    const int lb = (lane >> 3) & 1;
    const int lc = lane >> 4;
    const uint32_t a_off = (uint32_t)(la + lb * 8) * RSTRB + lc * 16;
    const uint32_t b_off = (uint32_t)(la + lc * 8) * RSTRB + lb * 16;

    const int arow = tid >> 1;
    const int ach  = (tid & 1) * 32;
    const int brw  = tid >> 2;
    const int bch  = (tid & 3) * 16;

    // warp phase offset for k-sub staggering
    const uint32_t kphase = (wid & 1) ? 32u : 0u;

    auto issue = [&](int kt) {
        const int k0 = kt * BK;
        const uint32_t base = sb + (kt % NSTAGE) * STG_B;
        const __half* ap = Ah + (size_t)(brow + arow) * K + k0 + ach / 2;
        const uint32_t adst = base + (uint32_t)arow * RSTRB + ach;
        CP16(adst,      ap);
        CP16(adst + 16, ap + 8);
        const size_t go = (size_t)(bcol + brw) * K + k0 + bch / 2;
        const uint32_t bdst = (uint32_t)brw * RSTRB + bch;
        CP16(base + OFF_BH + bdst, BhT + go);
        CP16(base + OFF_BM + bdst, BmT + go);
        CP_COMMIT();
    };

    #pragma unroll
    for (int mt = 0; mt < 4; mt++)
        #pragma unroll
        for (int nt = 0; nt < 4; nt++)
            #pragma unroll
            for (int r = 0; r < 4; r++) acc[mt][nt][r] = 0.0f;

    issue(0);
    issue(1);

    #pragma unroll 1
    for (int kt = 0; kt < NKSTEP; kt++) {
        CP_WAITG(1);
        __syncthreads();
        if (kt + 2 < NKSTEP) issue(kt + 2);

        const uint32_t sA  = sb + (kt % NSTAGE) * STG_B;
        const uint32_t sBh = sA + OFF_BH;
        const uint32_t sBm = sA + OFF_BM;
        const uint32_t arw = (uint32_t)(wm * 64) * RSTRB + a_off;
        const uint32_t brw_ = (uint32_t)(wn * 32) * RSTRB + b_off;

        #pragma unroll
        for (int ksub = 0; ksub < 2; ksub++) {
            const uint32_t kb = kphase ^ (ksub * 32);   // staggered order

            uint32_t a[4][4], bh[4][2], bm[4][2];

            #pragma unroll
            for (int mt = 0; mt < 4; mt++)
                LDSM_X4(a[mt][0], a[mt][1], a[mt][2], a[mt][3],
                        sA + arw + (uint32_t)(mt * 16) * RSTRB + kb);
            #pragma unroll
            for (int bp = 0; bp < 2; bp++)
                LDSM_X4(bh[2 * bp][0], bh[2 * bp][1], bh[2 * bp + 1][0], bh[2 * bp + 1][1],
                        sBh + brw_ + (uint32_t)(bp * 16) * RSTRB + kb);
            #pragma unroll
            for (int mt = 0; mt < 4; mt++)
                #pragma unroll
                for (int nt = 0; nt < 4; nt++)
                    mma16816(acc[mt][nt], a[mt], bh[nt][0], bh[nt][1]);

            #pragma unroll
            for (int bp = 0; bp < 2; bp++)
                LDSM_X4(bm[2 * bp][0], bm[2 * bp][1], bm[2 * bp + 1][0], bm[2 * bp + 1][1],
                        sBm + brw_ + (uint32_t)(bp * 16) * RSTRB + kb);
            #pragma unroll
            for (int mt = 0; mt < 4; mt++)
                #pragma unroll
                for (int nt = 0; nt < 4; nt++)
                    mma16816(acc[mt][nt], a[mt], bm[nt][0], bm[nt][1]);
        }
    }
}

// QKV with fused RoPE epilogue. z=0 -> q (hi), z=1 -> k (hi+mid), z=2 -> v (hi+mid)
__global__ __launch_bounds__(512, 1) void qkv_mma_kernel(const float* __restrict__ fc,
                                                         const float* __restrict__ fs)
{
    const int z = blockIdx.z;
    const __half* bh = (z == 0) ? g_wqh : (z == 1) ? g_wkh : g_wvh;
    const __half* bm = (z == 0) ? g_wqm : (z == 1) ? g_wkm : g_wvm;

    const int brow = blockIdx.y * BM;
    const int bcol = blockIdx.x * BN;

    float acc[4][4][4];
    hgemm_core(g_xh, bh, bm, brow, bcol, acc);

    const int lane = threadIdx.x & 31;
    const int wid  = threadIdx.x >> 5;
    const int gid  = lane >> 2;
    const int tq   = lane & 3;
    const int wm   = wid & 3;
    const int wn   = wid >> 2;

    #pragma unroll
    for (int mt = 0; mt < 4; mt++) {
        const int row0 = brow + wm * 64 + mt * 16 + gid;
        #pragma unroll
        for (int nt = 0; nt < 4; nt++) {
            const int col = bcol + wn * 32 + nt * 8 + tq * 2;
            const size_t o0 = (size_t)row0 * DIMV + col;
            const size_t o1 = (size_t)(row0 + 8) * DIMV + col;

            if (z == 2) {
                uint32_t h, m;
                split2h(acc[mt][nt][0], acc[mt][nt][1], h, m);
                *(uint32_t*)(g_vh + o0) = h;
                *(uint32_t*)(g_vm + o0) = m;
                split2h(acc[mt][nt][2], acc[mt][nt][3], h, m);
                *(uint32_t*)(g_vh + o1) = h;
                *(uint32_t*)(g_vm + o1) = m;
            } else {
                const int d  = (col & (HDIM - 1)) >> 1;
                const int s0 = row0 & (SEQ - 1);
                const int s1 = (row0 + 8) & (SEQ - 1);
                const float c0 = fc[s0 * 64 + d], n0 = fs[s0 * 64 + d];
                const float c1 = fc[s1 * 64 + d], n1 = fs[s1 * 64 + d];
                float r0 = acc[mt][nt][0] * c0 - acc[mt][nt][1] * n0;
                float i0 = acc[mt][nt][0] * n0 + acc[mt][nt][1] * c0;
                float r1 = acc[mt][nt][2] * c1 - acc[mt][nt][3] * n1;
                float i1 = acc[mt][nt][2] * n1 + acc[mt][nt][3] * c1;
                if (z == 0) {
                    *(uint32_t*)(g_qh + o0) = pack_h2(r0 * QSCALE, i0 * QSCALE);
                    *(uint32_t*)(g_qh + o1) = pack_h2(r1 * QSCALE, i1 * QSCALE);
                } else {
                    uint32_t h, m;
                    split2h(r0, i0, h, m);
                    *(uint32_t*)(g_kh + o0) = h;
                    *(uint32_t*)(g_km + o0) = m;
                    split2h(r1, i1, h, m);
                    *(uint32_t*)(g_kh + o1) = h;
                    *(uint32_t*)(g_km + o1) = m;
                }
            }
        }
    }
}

// oproj: A = attention out (fp16 hi), C = harness out (fp32)
__global__ __launch_bounds__(512, 1) void oproj_mma_kernel(float* __restrict__ out)
{
    const int brow = blockIdx.y * BM;
    const int bcol = blockIdx.x * BN;

    float acc[4][4][4];
    hgemm_core(g_aoh, g_woh, g_wom, brow, bcol, acc);

    const int lane = threadIdx.x & 31;
    const int wid  = threadIdx.x >> 5;
    const int gid  = lane >> 2;
    const int tq   = lane & 3;
    const int wm   = wid & 3;
    const int wn   = wid >> 2;

    #pragma unroll
    for (int mt = 0; mt < 4; mt++) {
        const int row0 = brow + wm * 64 + mt * 16 + gid;
        #pragma unroll
        for (int nt = 0; nt < 4; nt++) {
            const int col = bcol + wn * 32 + nt * 8 + tq * 2;
            *(float2*)(out + (size_t)row0 * DIMV + col) =
                make_float2(acc[mt][nt][0], acc[mt][nt][1]);
            *(float2*)(out + (size_t)(row0 + 8) * DIMV + col) =
                make_float2(acc[mt][nt][2], acc[mt][nt][3]);
        }
    }
}

// ---------------------------------------------------------------------------
// Tensor-core causal flash attention, fp16 2-product.
// CTA: 256 q-rows x one (b,h); 512 threads = 16 warps x 16 rows.
// KV tiles of 64, cp.async double-buffered, warp-staggered smem access.
// ---------------------------------------------------------------------------
constexpr int FBQ  = 256;
constexpr int QSTR = 272;
constexpr uint32_t FQH   = 0;
constexpr uint32_t FKV0  = (uint32_t)FBQ * QSTR;   // 69632
constexpr uint32_t KVMAT = 64u * QSTR;             // 17408
constexpr uint32_t KVSTG = 4u * KVMAT;             // 69632
constexpr int FSMEM = (int)(FKV0 + 2 * KVSTG);     // 208896

__global__ __launch_bounds__(512, 1) void flash_hmma_kernel()
{
    extern __shared__ char fsm[];
    const uint32_t sb = smem_u32(fsm);

    const int tid  = threadIdx.x;
    const int wid  = tid >> 5;       // 0..15
    const int lane = tid & 31;
    const int gid  = lane >> 2;
    const int tq   = lane & 3;

    const int qt = (int)gridDim.x - 1 - (int)blockIdx.x;  // big tiles first
    const int bh = blockIdx.y;
    const int b  = bh >> 4;
    const int h  = bh & (NH - 1);
    const size_t rowbase = (size_t)b * SEQ;
    const int    colbase = h * HDIM;

    const int la = lane & 7;
    const int lb = (lane >> 3) & 1;
    const int lc = lane >> 4;
    const uint32_t a_off = (uint32_t)(la + lb * 8) * QSTR + lc * 16;
    const uint32_t b_off = (uint32_t)(la + lc * 8) * QSTR + lb * 16;
    const uint32_t v_off = (uint32_t)(la + lb * 8) * QSTR + lc * 16;

    // staging maps (512 threads)
    const int qrow = tid >> 1;
    const int qseg = (tid & 1) * 8;
    const int krow = tid >> 3;
    const int kseg = (tid & 7) * 2;

    // ---- stage Q (hi) ----
    {
        const size_t qoff = (rowbase + qt * FBQ + qrow) * DIMV + colbase + qseg * 8;
        const uint32_t qdst = sb + FQH + (uint32_t)qrow * QSTR + qseg * 16;
        #pragma unroll
        for (int i = 0; i < 8; i++)
            CP16(qdst + 16 * i, g_qh + qoff + 8 * i);
    }

    auto issue_kv = [&](int j, int st) {
        const size_t goff = (rowbase + j * 64 + krow) * DIMV + colbase + kseg * 8;
        const uint32_t kdst = sb + FKV0 + st * KVSTG + (uint32_t)krow * QSTR + kseg * 16;
        #pragma unroll
        for (int i = 0; i < 2; i++) {
            CP16(kdst + 0 * KVMAT + 16 * i, g_kh + goff + 8 * i);
            CP16(kdst + 1 * KVMAT + 16 * i, g_km + goff + 8 * i);
            CP16(kdst + 2 * KVMAT + 16 * i, g_vh + goff + 8 * i);
            CP16(kdst + 3 * KVMAT + 16 * i, g_vm + goff + 8 * i);
        }
        CP_COMMIT();
    };

    issue_kv(0, 0);   // Q rides in this first group

    float o[16][4];
    #pragma unroll
    for (int i = 0; i < 16; i++)
        #pragma unroll
        for (int c = 0; c < 4; c++) o[i][c] = 0.0f;
    float m0 = -1e30f, m1 = -1e30f, l0 = 0.0f, l1 = 0.0f;

    const int row0 = qt * FBQ + wid * 16 + gid;
    const int jmax = 4 * qt + 3;

    for (int j = 0; j <= jmax; j++) {
        const int st = j & 1;
        CP_WAITG(0);
        __syncthreads();
        if (j + 1 <= jmax) issue_kv(j + 1, st ^ 1);

        const uint32_t kv = sb + FKV0 + st * KVSTG;

        // ---- S = Qh @ (Kh + Km)^T  (k-chunk order staggered by warp) ----
        float s[8][4];
        #pragma unroll
        for (int nt = 0; nt < 8; nt++)
            #pragma unroll
            for (int c = 0; c < 4; c++) s[nt][c] = 0.0f;

        const uint32_t qrow_off = (uint32_t)(wid * 16) * QSTR;
        #pragma unroll
        for (int t = 0; t < 8; t++) {
            const int tt = (t + wid) & 7;            // staggered
            const uint32_t kb = (uint32_t)tt * 32;
            uint32_t aq[4], bk[8][2];

            LDSM_X4(aq[0], aq[1], aq[2], aq[3], sb + FQH + qrow_off + a_off + kb);
            #pragma unroll
            for (int np = 0; np < 4; np++)
                LDSM_X4(bk[2 * np][0], bk[2 * np][1], bk[2 * np + 1][0], bk[2 * np + 1][1],
                        kv + 0 * KVMAT + (uint32_t)(np * 16) * QSTR + b_off + kb);
            #pragma unroll
            for (int nt = 0; nt < 8; nt++)
                mma16816(s[nt], aq, bk[nt][0], bk[nt][1]);

            #pragma unroll
            for (int np = 0; np < 4; np++)
                LDSM_X4(bk[2 * np][0], bk[2 * np][1], bk[2 * np + 1][0], bk[2 * np + 1][1],
                        kv + 1 * KVMAT + (uint32_t)(np * 16) * QSTR + b_off + kb);
            #pragma unroll
            for (int nt = 0; nt < 8; nt++)
                mma16816(s[nt], aq, bk[nt][0], bk[nt][1]);
        }

        // ---- causal mask ----
        if (j * 64 + 63 > qt * FBQ + wid * 16) {
            #pragma unroll
            for (int nt = 0; nt < 8; nt++) {
                const int col = j * 64 + nt * 8 + tq * 2;
                if (col     > row0)     s[nt][0] = -1e30f;
                if (col + 1 > row0)     s[nt][1] = -1e30f;
                if (col     > row0 + 8) s[nt][2] = -1e30f;
                if (col + 1 > row0 + 8) s[nt][3] = -1e30f;
            }
        }

        // ---- online softmax ----
        float mx0 = m0, mx1 = m1;
        #pragma unroll
        for (int nt = 0; nt < 8; nt++) {
            mx0 = fmaxf(mx0, fmaxf(s[nt][0], s[nt][1]));
            mx1 = fmaxf(mx1, fmaxf(s[nt][2], s[nt][3]));
        }
        mx0 = fmaxf(mx0, __shfl_xor_sync(0xffffffffu, mx0, 1));
        mx0 = fmaxf(mx0, __shfl_xor_sync(0xffffffffu, mx0, 2));
        mx1 = fmaxf(mx1, __shfl_xor_sync(0xffffffffu, mx1, 1));
        mx1 = fmaxf(mx1, __shfl_xor_sync(0xffffffffu, mx1, 2));

        const float al0 = ex2f((m0 - mx0) * L2E);
        const float al1 = ex2f((m1 - mx1) * L2E);
        m0 = mx0; m1 = mx1;

        uint32_t ph[8][2];
        float sum0 = 0.0f, sum1 = 0.0f;
        #pragma unroll
        for (int nt = 0; nt < 8; nt++) {
            float p00 = ex2f((s[nt][0] - m0) * L2E);
            float p01 = ex2f((s[nt][1] - m0) * L2E);
            float p10 = ex2f((s[nt][2] - m1) * L2E);
            float p11 = ex2f((s[nt][3] - m1) * L2E);
            sum0 += p00 + p01;
            sum1 += p10 + p11;
            ph[nt][0] = pack_h2(p00, p01);
            ph[nt][1] = pack_h2(p10, p11);
        }
        sum0 += __shfl_xor_sync(0xffffffffu, sum0, 1);
        sum0 += __shfl_xor_sync(0xffffffffu, sum0, 2);
        sum1 += __shfl_xor_sync(0xffffffffu, sum1, 1);
        sum1 += __shfl_xor_sync(0xffffffffu, sum1, 2);
        l0 = l0 * al0 + sum0;
        l1 = l1 * al1 + sum1;

        #pragma unroll
        for (int i = 0; i < 16; i++) {
            o[i][0] *= al0; o[i][1] *= al0;
            o[i][2] *= al1; o[i][3] *= al1;
        }

        // ---- O += Ph @ (Vh + Vm)  (t order staggered by warp) ----
        #pragma unroll
        for (int t = 0; t < 4; t++) {
            const int t2 = (t + wid) & 3;            // staggered
            uint32_t aph[4] = { ph[2 * t2][0], ph[2 * t2][1],
                                ph[2 * t2 + 1][0], ph[2 * t2 + 1][1] };
            uint32_t bv[16][2];

            #pragma unroll
            for (int vn = 0; vn < 8; vn++)
                LDSM_X4_T(bv[2 * vn][0], bv[2 * vn][1], bv[2 * vn + 1][0], bv[2 * vn + 1][1],
                          kv + 2 * KVMAT + (uint32_t)(t2 * 16) * QSTR + (uint32_t)(vn * 16) * 2 + v_off);
            #pragma unroll
            for (int n = 0; n < 16; n++)
                mma16816(o[n], aph, bv[n][0], bv[n][1]);

            #pragma unroll
            for (int vn = 0; vn < 8; vn++)
                LDSM_X4_T(bv[2 * vn][0], bv[2 * vn][1], bv[2 * vn + 1][0], bv[2 * vn + 1][1],
                          kv + 3 * KVMAT + (uint32_t)(t2 * 16) * QSTR + (uint32_t)(vn * 16) * 2 + v_off);
            #pragma unroll
            for (int n = 0; n < 16; n++)
                mma16816(o[n], aph, bv[n][0], bv[n][1]);
        }
    }

    // ---- epilogue ----
    const float inv0 = 1.0f / l0;
    const float inv1 = 1.0f / l1;
    #pragma unroll
    for (int n = 0; n < 16; n++) {
        const int col = colbase + n * 8 + tq * 2;
        *(uint32_t*)(g_aoh + (rowbase + row0) * DIMV + col) =
            pack_h2(o[n][0] * inv0, o[n][1] * inv0);
        *(uint32_t*)(g_aoh + (rowbase + row0 + 8) * DIMV + col) =
            pack_h2(o[n][2] * inv1, o[n][3] * inv1);
    }
}

// ---------------------------------------------------------------------------
extern "C" void kernel_launch(void* const* d_in, const int* in_sizes, int n_in,
                              void* d_out, int out_size)
{
    const float* x  = (const float*)d_in[0];
    const float* fc = (const float*)d_in[1];
    const float* fs = (const float*)d_in[2];
    // d_in[3] = mask (causal applied analytically)
    const float* wq = (const float*)d_in[4];
    const float* wk = (const float*)d_in[5];
    const float* wv = (const float*)d_in[6];
    const float* wo = (const float*)d_in[7];
    float* out = (float*)d_out;

    cudaFuncSetAttribute(flash_hmma_kernel,
                         cudaFuncAttributeMaxDynamicSharedMemorySize, FSMEM);
    cudaFuncSetAttribute(qkv_mma_kernel,
                         cudaFuncAttributeMaxDynamicSharedMemorySize, GSMEM);
    cudaFuncSetAttribute(oproj_mma_kernel,
                         cudaFuncAttributeMaxDynamicSharedMemorySize, GSMEM);

    // 1) split inputs + weights (single launch: z=0..3 weights, z=4 x)
    dim3 sg(DIMV / 32, DIMV / 32, 5);
    dim3 sbk(32, 8);
    split_all_kernel<<<sg, sbk>>>(x, wq, wk, wv, wo);

    // 2) QKV projections with fused RoPE epilogue (512 threads, staggered)
    qkv_mma_kernel<<<dim3(DIMV / BN, MROWS / BM, 3), 512, GSMEM>>>(fc, fs);

    // 3) Causal flash attention (512 threads, staggered)
    flash_hmma_kernel<<<dim3(SEQ / FBQ, BATCH * NH), 512, FSMEM>>>();

    // 4) output projection (512 threads, staggered)
    oproj_mma_kernel<<<dim3(DIMV / BN, MROWS / BM), 512, GSMEM>>>(out);
}

// round 17
// speedup vs baseline: 1.5510x; 1.5510x over previous
#include <cuda_runtime.h>
#include <cuda_fp16.h>
#include <cstdint>
#include <math.h>

// Problem constants
constexpr int BATCH = 2;
constexpr int SEQ   = 2048;
constexpr int DIMV  = 2048;
constexpr int NH    = 16;
constexpr int HDIM  = 128;
constexpr int MROWS = BATCH * SEQ;  // 4096
constexpr float QSCALE = 0.08838834764831845f;  // 1/sqrt(128)
constexpr float L2E    = 1.4426950408889634f;

// ---------------------------------------------------------------------------
// Device-global scratch. RULE (R3-R5 bug): device globals must NEVER be passed
// as kernel arguments from host code — GB300 ATS silently accepts the host
// shadow address. Reference them inside kernels only.
// ---------------------------------------------------------------------------
__device__ __half g_xh [MROWS * DIMV];   // fp16(x)
__device__ __half g_qh [MROWS * DIMV];   // fp16(roped,scaled q)
__device__ __half g_kh [MROWS * DIMV];   // fp16(roped k)
__device__ __half g_vh [MROWS * DIMV];   // fp16(v)
__device__ __half g_aoh[MROWS * DIMV];   // fp16(attention out)

// Transposed fp16 weights: [N=2048][K=2048] K-major, value = W[k][n]
__device__ __half g_wqh[DIMV * DIMV];
__device__ __half g_wkh[DIMV * DIMV];
__device__ __half g_wvh[DIMV * DIMV];
__device__ __half g_woh[DIMV * DIMV];

// ---------------------------------------------------------------------------
// helpers
// ---------------------------------------------------------------------------
__device__ __forceinline__ uint32_t smem_u32(const void* p) {
    uint32_t a;
    asm("{ .reg .u64 t; cvta.to.shared.u64 t, %1; cvt.u32.u64 %0, t; }"
        : "=r"(a) : "l"(p));
    return a;
}

__device__ __forceinline__ void mma16816(float d[4], const uint32_t a[4],
                                         const uint32_t b0, const uint32_t b1) {
    asm volatile(
        "mma.sync.aligned.m16n8k16.row.col.f32.f16.f16.f32 "
        "{%0,%1,%2,%3}, {%4,%5,%6,%7}, {%8,%9}, {%0,%1,%2,%3};"
        : "+f"(d[0]), "+f"(d[1]), "+f"(d[2]), "+f"(d[3])
        : "r"(a[0]), "r"(a[1]), "r"(a[2]), "r"(a[3]), "r"(b0), "r"(b1));
}

#define LDSM_X4(r0, r1, r2, r3, addr)                                  \
    asm volatile("ldmatrix.sync.aligned.m8n8.x4.shared.b16 "           \
                 "{%0,%1,%2,%3}, [%4];"                                \
                 : "=r"(r0), "=r"(r1), "=r"(r2), "=r"(r3) : "r"(addr))

#define LDSM_X4_T(r0, r1, r2, r3, addr)                                \
    asm volatile("ldmatrix.sync.aligned.m8n8.x4.trans.shared.b16 "     \
                 "{%0,%1,%2,%3}, [%4];"                                \
                 : "=r"(r0), "=r"(r1), "=r"(r2), "=r"(r3) : "r"(addr))

#define CP16(dst, src)                                                 \
    asm volatile("cp.async.cg.shared.global [%0], [%1], 16;"           \
                 :: "r"(dst), "l"(src) : "memory")
#define CP_COMMIT()  asm volatile("cp.async.commit_group;" ::: "memory")
#define CP_WAITG(n)  asm volatile("cp.async.wait_group %0;" :: "n"(n) : "memory")

__device__ __forceinline__ float ex2f(float x) {
    float y;
    asm("ex2.approx.ftz.f32 %0, %1;" : "=f"(y) : "f"(x));
    return y;
}

__device__ __forceinline__ uint32_t pack_h2(float x, float y) {
    __half2 h = __floats2half2_rn(x, y);
    return *reinterpret_cast<uint32_t*>(&h);
}

// ---------------------------------------------------------------------------
// Combined split kernel:
//   z in [0,3]: weight transpose (w [K,N] fp32 -> [N,K] fp16)
//   z == 4    : x -> g_xh (fp16)
// ---------------------------------------------------------------------------
__global__ void split_all_kernel(const float* __restrict__ x,
                                 const float* __restrict__ wq,
                                 const float* __restrict__ wk,
                                 const float* __restrict__ wv,
                                 const float* __restrict__ wo)
{
    const int z = blockIdx.z;
    const int tid = threadIdx.y * 32 + threadIdx.x;

    if (z == 4) {
        const int blk = blockIdx.y * gridDim.x + blockIdx.x;
        const int base = blk * 512 + tid;
        #pragma unroll
        for (int r = 0; r < 2; r++) {
            const int i = base + r * 256;
            float4 v = ((const float4*)x)[i];
            ((uint2*)g_xh)[i] = make_uint2(pack_h2(v.x, v.y), pack_h2(v.z, v.w));
        }
        return;
    }

    const float* w = (z == 0) ? wq : (z == 1) ? wk : (z == 2) ? wv : wo;
    __half* whT = (z == 0) ? g_wqh : (z == 1) ? g_wkh : (z == 2) ? g_wvh : g_woh;

    __shared__ float t[32][33];
    const int n0 = blockIdx.x * 32;
    const int k0 = blockIdx.y * 32;
    const int tx = threadIdx.x;
    const int ty = threadIdx.y;
    #pragma unroll
    for (int i = ty; i < 32; i += 8)
        t[i][tx] = w[(size_t)(k0 + i) * DIMV + n0 + tx];
    __syncthreads();
    #pragma unroll
    for (int i = ty; i < 32; i += 8)
        whT[(size_t)(n0 + i) * DIMV + k0 + tx] = __float2half_rn(t[tx][i]);
}

// ---------------------------------------------------------------------------
// Pure fp16 GEMM core: D = A @ W (both fp16, fp32 accum). cp.async 3-stage.
// CTA 256x128, BK=32, 512 threads = 16 warps (4m x 4n), warp tile 64x32.
// ---------------------------------------------------------------------------
constexpr int BM = 256, BN = 128, BK = 32;
constexpr int RSTRB   = 80;
constexpr int TILE_A  = 256 * RSTRB;          // 20480
constexpr int TILE_B  = 128 * RSTRB;          // 10240
constexpr int OFF_B   = TILE_A;
constexpr int STG_B   = TILE_A + TILE_B;      // 30720
constexpr int NSTAGE  = 3;
constexpr int GSMEM   = NSTAGE * STG_B;       // 92160
constexpr int NKSTEP  = DIMV / BK;            // 64

__device__ __forceinline__ void hgemm_core(const __half* __restrict__ Ah,
                                           const __half* __restrict__ BhT,
                                           int brow, int bcol,
                                           float acc[4][4][4])
{
    extern __shared__ char smem[];
    constexpr int K = DIMV;
    const uint32_t sb = smem_u32(smem);

    const int tid  = threadIdx.x;
    const int wid  = tid >> 5;
    const int lane = tid & 31;
    const int wm   = wid & 3;
    const int wn   = wid >> 2;

    const int la = lane & 7;
    const int lb = (lane >> 3) & 1;
    const int lc = lane >> 4;
    const uint32_t a_off = (uint32_t)(la + lb * 8) * RSTRB + lc * 16;
    const uint32_t b_off = (uint32_t)(la + lc * 8) * RSTRB + lb * 16;

    // staging (512 threads, 3 CP16 each): A 1024 chunks, B 512 chunks
    const int arow = tid >> 1;                 // 0..255 (2 chunks each)
    const int ach  = (tid & 1) * 32;
    const int brw  = tid >> 2;                 // 0..127 (1 chunk each)
    const int bch  = (tid & 3) * 16;

    auto issue = [&](int kt) {
        const int k0 = kt * BK;
        const uint32_t base = sb + (kt % NSTAGE) * STG_B;
        const __half* ap = Ah + (size_t)(brow + arow) * K + k0 + ach / 2;
        const uint32_t adst = base + (uint32_t)arow * RSTRB + ach;
        CP16(adst,      ap);
        CP16(adst + 16, ap + 8);
        const size_t go = (size_t)(bcol + brw) * K + k0 + bch / 2;
        CP16(base + OFF_B + (uint32_t)brw * RSTRB + bch, BhT + go);
        CP_COMMIT();
    };

    #pragma unroll
    for (int mt = 0; mt < 4; mt++)
        #pragma unroll
        for (int nt = 0; nt < 4; nt++)
            #pragma unroll
            for (int r = 0; r < 4; r++) acc[mt][nt][r] = 0.0f;

    issue(0);
    issue(1);

    #pragma unroll 1
    for (int kt = 0; kt < NKSTEP; kt++) {
        CP_WAITG(1);
        __syncthreads();
        if (kt + 2 < NKSTEP) issue(kt + 2);

        const uint32_t sA  = sb + (kt % NSTAGE) * STG_B;
        const uint32_t sB  = sA + OFF_B;
        const uint32_t arw = (uint32_t)(wm * 64) * RSTRB + a_off;
        const uint32_t brw_ = (uint32_t)(wn * 32) * RSTRB + b_off;

        #pragma unroll
        for (int ksub = 0; ksub < 2; ksub++) {
            const uint32_t kb = ksub * 32;

            uint32_t a[4][4], bh[4][2];

            #pragma unroll
            for (int mt = 0; mt < 4; mt++)
                LDSM_X4(a[mt][0], a[mt][1], a[mt][2], a[mt][3],
                        sA + arw + (uint32_t)(mt * 16) * RSTRB + kb);
            #pragma unroll
            for (int bp = 0; bp < 2; bp++)
                LDSM_X4(bh[2 * bp][0], bh[2 * bp][1], bh[2 * bp + 1][0], bh[2 * bp + 1][1],
                        sB + brw_ + (uint32_t)(bp * 16) * RSTRB + kb);
            #pragma unroll
            for (int mt = 0; mt < 4; mt++)
                #pragma unroll
                for (int nt = 0; nt < 4; nt++)
                    mma16816(acc[mt][nt], a[mt], bh[nt][0], bh[nt][1]);
        }
    }
}

// QKV with fused RoPE epilogue. z=0 -> q, z=1 -> k, z=2 -> v (all fp16)
__global__ __launch_bounds__(512, 1) void qkv_mma_kernel(const float* __restrict__ fc,
                                                         const float* __restrict__ fs)
{
    const int z = blockIdx.z;
    const __half* bh = (z == 0) ? g_wqh : (z == 1) ? g_wkh : g_wvh;

    const int brow = blockIdx.y * BM;
    const int bcol = blockIdx.x * BN;

    float acc[4][4][4];
    hgemm_core(g_xh, bh, brow, bcol, acc);

    const int lane = threadIdx.x & 31;
    const int wid  = threadIdx.x >> 5;
    const int gid  = lane >> 2;
    const int tq   = lane & 3;
    const int wm   = wid & 3;
    const int wn   = wid >> 2;

    #pragma unroll
    for (int mt = 0; mt < 4; mt++) {
        const int row0 = brow + wm * 64 + mt * 16 + gid;
        #pragma unroll
        for (int nt = 0; nt < 4; nt++) {
            const int col = bcol + wn * 32 + nt * 8 + tq * 2;
            const size_t o0 = (size_t)row0 * DIMV + col;
            const size_t o1 = (size_t)(row0 + 8) * DIMV + col;

            if (z == 2) {
                *(uint32_t*)(g_vh + o0) = pack_h2(acc[mt][nt][0], acc[mt][nt][1]);
                *(uint32_t*)(g_vh + o1) = pack_h2(acc[mt][nt][2], acc[mt][nt][3]);
            } else {
                const int d  = (col & (HDIM - 1)) >> 1;
                const int s0 = row0 & (SEQ - 1);
                const int s1 = (row0 + 8) & (SEQ - 1);
                const float c0 = fc[s0 * 64 + d], n0 = fs[s0 * 64 + d];
                const float c1 = fc[s1 * 64 + d], n1 = fs[s1 * 64 + d];
                float r0 = acc[mt][nt][0] * c0 - acc[mt][nt][1] * n0;
                float i0 = acc[mt][nt][0] * n0 + acc[mt][nt][1] * c0;
                float r1 = acc[mt][nt][2] * c1 - acc[mt][nt][3] * n1;
                float i1 = acc[mt][nt][2] * n1 + acc[mt][nt][3] * c1;
                if (z == 0) {
                    *(uint32_t*)(g_qh + o0) = pack_h2(r0 * QSCALE, i0 * QSCALE);
                    *(uint32_t*)(g_qh + o1) = pack_h2(r1 * QSCALE, i1 * QSCALE);
                } else {
                    *(uint32_t*)(g_kh + o0) = pack_h2(r0, i0);
                    *(uint32_t*)(g_kh + o1) = pack_h2(r1, i1);
                }
            }
        }
    }
}

// oproj: A = attention out (fp16), C = harness out (fp32)
__global__ __launch_bounds__(512, 1) void oproj_mma_kernel(float* __restrict__ out)
{
    const int brow = blockIdx.y * BM;
    const int bcol = blockIdx.x * BN;

    float acc[4][4][4];
    hgemm_core(g_aoh, g_woh, brow, bcol, acc);

    const int lane = threadIdx.x & 31;
    const int wid  = threadIdx.x >> 5;
    const int gid  = lane >> 2;
    const int tq   = lane & 3;
    const int wm   = wid & 3;
    const int wn   = wid >> 2;

    #pragma unroll
    for (int mt = 0; mt < 4; mt++) {
        const int row0 = brow + wm * 64 + mt * 16 + gid;
        #pragma unroll
        for (int nt = 0; nt < 4; nt++) {
            const int col = bcol + wn * 32 + nt * 8 + tq * 2;
            *(float2*)(out + (size_t)row0 * DIMV + col) =
                make_float2(acc[mt][nt][0], acc[mt][nt][1]);
            *(float2*)(out + (size_t)(row0 + 8) * DIMV + col) =
                make_float2(acc[mt][nt][2], acc[mt][nt][3]);
        }
    }
}

// ---------------------------------------------------------------------------
// Tensor-core causal flash attention, pure fp16 operands.
// CTA: 256 q-rows x one (b,h); 512 threads = 16 warps x 16 rows.
// KV tiles of 64 (K + V only), cp.async double-buffered.
// ---------------------------------------------------------------------------
constexpr int FBQ  = 256;
constexpr int QSTR = 272;
constexpr uint32_t FQH   = 0;
constexpr uint32_t FKV0  = (uint32_t)FBQ * QSTR;   // 69632
constexpr uint32_t KVMAT = 64u * QSTR;             // 17408
constexpr uint32_t KVSTG = 2u * KVMAT;             // 34816 (Kh, Vh)
constexpr int FSMEM = (int)(FKV0 + 2 * KVSTG);     // 139264

__global__ __launch_bounds__(512, 1) void flash_hmma_kernel()
{
    extern __shared__ char fsm[];
    const uint32_t sb = smem_u32(fsm);

    const int tid  = threadIdx.x;
    const int wid  = tid >> 5;       // 0..15
    const int lane = tid & 31;
    const int gid  = lane >> 2;
    const int tq   = lane & 3;

    const int qt = (int)gridDim.x - 1 - (int)blockIdx.x;  // big tiles first
    const int bh = blockIdx.y;
    const int b  = bh >> 4;
    const int h  = bh & (NH - 1);
    const size_t rowbase = (size_t)b * SEQ;
    const int    colbase = h * HDIM;

    const int la = lane & 7;
    const int lb = (lane >> 3) & 1;
    const int lc = lane >> 4;
    const uint32_t a_off = (uint32_t)(la + lb * 8) * QSTR + lc * 16;
    const uint32_t b_off = (uint32_t)(la + lc * 8) * QSTR + lb * 16;
    const uint32_t v_off = (uint32_t)(la + lb * 8) * QSTR + lc * 16;

    // staging maps (512 threads)
    const int qrow = tid >> 1;                  // 2 threads/row
    const int qseg = (tid & 1) * 8;
    const int krow = tid >> 3;                  // 8 threads/row
    const int kseg = (tid & 7) * 2;             // 2 x 16B per matrix

    // ---- stage Q ----
    {
        const size_t qoff = (rowbase + qt * FBQ + qrow) * DIMV + colbase + qseg * 8;
        const uint32_t qdst = sb + FQH + (uint32_t)qrow * QSTR + qseg * 16;
        #pragma unroll
        for (int i = 0; i < 8; i++)
            CP16(qdst + 16 * i, g_qh + qoff + 8 * i);
    }

    auto issue_kv = [&](int j, int st) {
        const size_t goff = (rowbase + j * 64 + krow) * DIMV + colbase + kseg * 8;
        const uint32_t kdst = sb + FKV0 + st * KVSTG + (uint32_t)krow * QSTR + kseg * 16;
        #pragma unroll
        for (int i = 0; i < 2; i++) {
            CP16(kdst + 0 * KVMAT + 16 * i, g_kh + goff + 8 * i);
            CP16(kdst + 1 * KVMAT + 16 * i, g_vh + goff + 8 * i);
        }
        CP_COMMIT();
    };

    issue_kv(0, 0);   // Q rides in this first group

    float o[16][4];
    #pragma unroll
    for (int i = 0; i < 16; i++)
        #pragma unroll
        for (int c = 0; c < 4; c++) o[i][c] = 0.0f;
    float m0 = -1e30f, m1 = -1e30f, l0 = 0.0f, l1 = 0.0f;

    const int row0 = qt * FBQ + wid * 16 + gid;
    const int jmax = 4 * qt + 3;

    for (int j = 0; j <= jmax; j++) {
        const int st = j & 1;
        CP_WAITG(0);
        __syncthreads();
        if (j + 1 <= jmax) issue_kv(j + 1, st ^ 1);

        const uint32_t kv = sb + FKV0 + st * KVSTG;

        // ---- S = Q @ K^T ----
        float s[8][4];
        #pragma unroll
        for (int nt = 0; nt < 8; nt++)
            #pragma unroll
            for (int c = 0; c < 4; c++) s[nt][c] = 0.0f;

        const uint32_t qrow_off = (uint32_t)(wid * 16) * QSTR;
        #pragma unroll
        for (int t = 0; t < 8; t++) {
            const uint32_t kb = t * 32;
            uint32_t aq[4], bk[8][2];

            LDSM_X4(aq[0], aq[1], aq[2], aq[3], sb + FQH + qrow_off + a_off + kb);
            #pragma unroll
            for (int np = 0; np < 4; np++)
                LDSM_X4(bk[2 * np][0], bk[2 * np][1], bk[2 * np + 1][0], bk[2 * np + 1][1],
                        kv + 0 * KVMAT + (uint32_t)(np * 16) * QSTR + b_off + kb);
            #pragma unroll
            for (int nt = 0; nt < 8; nt++)
                mma16816(s[nt], aq, bk[nt][0], bk[nt][1]);
        }

        // ---- causal mask ----
        if (j * 64 + 63 > qt * FBQ + wid * 16) {
            #pragma unroll
            for (int nt = 0; nt < 8; nt++) {
                const int col = j * 64 + nt * 8 + tq * 2;
                if (col     > row0)     s[nt][0] = -1e30f;
                if (col + 1 > row0)     s[nt][1] = -1e30f;
                if (col     > row0 + 8) s[nt][2] = -1e30f;
                if (col + 1 > row0 + 8) s[nt][3] = -1e30f;
            }
        }

        // ---- online softmax ----
        float mx0 = m0, mx1 = m1;
        #pragma unroll
        for (int nt = 0; nt < 8; nt++) {
            mx0 = fmaxf(mx0, fmaxf(s[nt][0], s[nt][1]));
            mx1 = fmaxf(mx1, fmaxf(s[nt][2], s[nt][3]));
        }
        mx0 = fmaxf(mx0, __shfl_xor_sync(0xffffffffu, mx0, 1));
        mx0 = fmaxf(mx0, __shfl_xor_sync(0xffffffffu, mx0, 2));
        mx1 = fmaxf(mx1, __shfl_xor_sync(0xffffffffu, mx1, 1));
        mx1 = fmaxf(mx1, __shfl_xor_sync(0xffffffffu, mx1, 2));

        const float al0 = ex2f((m0 - mx0) * L2E);
        const float al1 = ex2f((m1 - mx1) * L2E);
        m0 = mx0; m1 = mx1;

        uint32_t ph[8][2];
        float sum0 = 0.0f, sum1 = 0.0f;
        #pragma unroll
        for (int nt = 0; nt < 8; nt++) {
            float p00 = ex2f((s[nt][0] - m0) * L2E);
            float p01 = ex2f((s[nt][1] - m0) * L2E);
            float p10 = ex2f((s[nt][2] - m1) * L2E);
            float p11 = ex2f((s[nt][3] - m1) * L2E);
            sum0 += p00 + p01;
            sum1 += p10 + p11;
            ph[nt][0] = pack_h2(p00, p01);
            ph[nt][1] = pack_h2(p10, p11);
        }
        sum0 += __shfl_xor_sync(0xffffffffu, sum0, 1);
        sum0 += __shfl_xor_sync(0xffffffffu, sum0, 2);
        sum1 += __shfl_xor_sync(0xffffffffu, sum1, 1);
        sum1 += __shfl_xor_sync(0xffffffffu, sum1, 2);
        l0 = l0 * al0 + sum0;
        l1 = l1 * al1 + sum1;

        #pragma unroll
        for (int i = 0; i < 16; i++) {
            o[i][0] *= al0; o[i][1] *= al0;
            o[i][2] *= al1; o[i][3] *= al1;
        }

        // ---- O += P @ V ----
        #pragma unroll
        for (int t = 0; t < 4; t++) {
            uint32_t aph[4] = { ph[2 * t][0], ph[2 * t][1],
                                ph[2 * t + 1][0], ph[2 * t + 1][1] };
            uint32_t bv[16][2];

            #pragma unroll
            for (int vn = 0; vn < 8; vn++)
                LDSM_X4_T(bv[2 * vn][0], bv[2 * vn][1], bv[2 * vn + 1][0], bv[2 * vn + 1][1],
                          kv + 1 * KVMAT + (uint32_t)(t * 16) * QSTR + (uint32_t)(vn * 16) * 2 + v_off);
            #pragma unroll
            for (int n = 0; n < 16; n++)
                mma16816(o[n], aph, bv[n][0], bv[n][1]);
        }
    }

    // ---- epilogue ----
    const float inv0 = 1.0f / l0;
    const float inv1 = 1.0f / l1;
    #pragma unroll
    for (int n = 0; n < 16; n++) {
        const int col = colbase + n * 8 + tq * 2;
        *(uint32_t*)(g_aoh + (rowbase + row0) * DIMV + col) =
            pack_h2(o[n][0] * inv0, o[n][1] * inv0);
        *(uint32_t*)(g_aoh + (rowbase + row0 + 8) * DIMV + col) =
            pack_h2(o[n][2] * inv1, o[n][3] * inv1);
    }
}

// ---------------------------------------------------------------------------
extern "C" void kernel_launch(void* const* d_in, const int* in_sizes, int n_in,
                              void* d_out, int out_size)
{
    const float* x  = (const float*)d_in[0];
    const float* fc = (const float*)d_in[1];
    const float* fs = (const float*)d_in[2];
    // d_in[3] = mask (causal applied analytically)
    const float* wq = (const float*)d_in[4];
    const float* wk = (const float*)d_in[5];
    const float* wv = (const float*)d_in[6];
    const float* wo = (const float*)d_in[7];
    float* out = (float*)d_out;

    cudaFuncSetAttribute(flash_hmma_kernel,
                         cudaFuncAttributeMaxDynamicSharedMemorySize, FSMEM);
    cudaFuncSetAttribute(qkv_mma_kernel,
                         cudaFuncAttributeMaxDynamicSharedMemorySize, GSMEM);
    cudaFuncSetAttribute(oproj_mma_kernel,
                         cudaFuncAttributeMaxDynamicSharedMemorySize, GSMEM);

    // 1) convert inputs + weights to fp16 (single launch)
    dim3 sg(DIMV / 32, DIMV / 32, 5);
    dim3 sbk(32, 8);
    split_all_kernel<<<sg, sbk>>>(x, wq, wk, wv, wo);

    // 2) QKV projections with fused RoPE epilogue
    qkv_mma_kernel<<<dim3(DIMV / BN, MROWS / BM, 3), 512, GSMEM>>>(fc, fs);

    // 3) Causal flash attention
    flash_hmma_kernel<<<dim3(SEQ / FBQ, BATCH * NH), 512, FSMEM>>>();

    // 4) output projection
    oproj_mma_kernel<<<dim3(DIMV / BN, MROWS / BM), 512, GSMEM>>>(out);
}